// round 3
// baseline (speedup 1.0000x reference)
#include <cuda_runtime.h>

// Dirichlet Jacobi step:
//   out[b,i,j] = 0                                    if i,j on boundary
//   out[b,i,j] = 0.25*(v[i-1,j]+v[i+1,j]+v[i,j-1]+v[i,j+1]) + cof*f[b,i,j]
// where v == u with the boundary ring forced to 0, cof = -(1/1023)^2/4.
//
// Layout: B=16, H=W=1024, fp32. One CTA per (batch,row): 256 threads x float4.
// Purely HBM-bound: ~201 MB total traffic -> ~26-30 us roofline on GB300.

#define GRID_W 1024
#define GRID_H 1024
#define BATCH  16

__global__ __launch_bounds__(256, 8)
void jacobi_dirichlet_kernel(const float* __restrict__ u,
                             const float* __restrict__ f,
                             float* __restrict__ out)
{
    const int row = blockIdx.x & (GRID_H - 1);
    const int b   = blockIdx.x >> 10;
    const int t   = threadIdx.x;          // 0..255
    const int j0  = t << 2;               // first column this thread owns

    const size_t rowBase = ((size_t)b * GRID_H + row) * GRID_W;
    float4* out4 = reinterpret_cast<float4*>(out + rowBase) + t;

    // Boundary rows: entire row is the Dirichlet value (0).
    if (row == 0 || row == GRID_H - 1) {
        *out4 = make_float4(0.f, 0.f, 0.f, 0.f);
        return;
    }

    // ---- center row into shared memory, with zeroed ring (cols 0,1023) and
    //      zero halo at [-1] and [1024] so shifted reads need no branches.
    __shared__ float smbuf[GRID_W + 2];
    float* sm = smbuf + 1;

    float4 c4 = *(reinterpret_cast<const float4*>(u + rowBase) + t);
    if (t == 0)   { c4.x = 0.f; sm[-1]      = 0.f; }
    if (t == 255) { c4.w = 0.f; sm[GRID_W]  = 0.f; }
    sm[j0 + 0] = c4.x;
    sm[j0 + 1] = c4.y;
    sm[j0 + 2] = c4.z;
    sm[j0 + 3] = c4.w;

    // ---- vertical neighbors (v is 0 on rows 0 and 1023)
    float4 up4, dn4;
    if (row == 1)            up4 = make_float4(0.f, 0.f, 0.f, 0.f);
    else                     up4 = *(reinterpret_cast<const float4*>(u + rowBase - GRID_W) + t);
    if (row == GRID_H - 2)   dn4 = make_float4(0.f, 0.f, 0.f, 0.f);
    else                     dn4 = *(reinterpret_cast<const float4*>(u + rowBase + GRID_W) + t);

    float4 f4 = *(reinterpret_cast<const float4*>(f + rowBase) + t);

    __syncthreads();

    const float cof = -(1.0f / 1023.0f) * (1.0f / 1023.0f) * 0.25f;

    float4 r;
    r.x = 0.25f * (up4.x + dn4.x + sm[j0 - 1] + sm[j0 + 1]) + cof * f4.x;
    r.y = 0.25f * (up4.y + dn4.y + sm[j0 + 0] + sm[j0 + 2]) + cof * f4.y;
    r.z = 0.25f * (up4.z + dn4.z + sm[j0 + 1] + sm[j0 + 3]) + cof * f4.z;
    r.w = 0.25f * (up4.w + dn4.w + sm[j0 + 2] + sm[j0 + 4]) + cof * f4.w;

    // Boundary columns stay at the Dirichlet value.
    if (t == 0)   r.x = 0.f;
    if (t == 255) r.w = 0.f;

    *out4 = r;
}

extern "C" void kernel_launch(void* const* d_in, const int* in_sizes, int n_in,
                              void* d_out, int out_size)
{
    const float* u = (const float*)d_in[0];
    const float* f = (const float*)d_in[1];
    // d_in[2] is the fixed 3x3 stencil (0.25 cross) — hardcoded in the kernel.
    float* out = (float*)d_out;

    dim3 grid(BATCH * GRID_H);
    dim3 block(256);
    jacobi_dirichlet_kernel<<<grid, block>>>(u, f, out);
}

// round 4
// speedup vs baseline: 1.0077x; 1.0077x over previous
#include <cuda_runtime.h>

// Dirichlet Jacobi step, register-rolling warp-strip version.
//   out[b,i,j] = 0 on the boundary ring
//   out[b,i,j] = 0.25*(v_up+v_dn+v_lf+v_rt) + cof*f   in the interior,
// where v = u with boundary ring forced to 0, cof = -(1/1023)^2/4.
//
// Decomposition: each warp owns a 128-column strip (8 strips per row) and
// sweeps ROWS_PER_WARP rows, rolling prev/cur/next u-rows through registers.
// Horizontal neighbors come from the float4 lanes + 2 warp shuffles; warp-strip
// edges are 2 predicated scalar loads (L2 hits). No shared memory, no barriers.

#define GRID_W 1024
#define GRID_H 1024
#define BATCH  16
#define ROWS_PER_WARP 8
#define COLBLOCKS 8              // 1024 / 128 cols per warp
#define STRIPS (GRID_H / ROWS_PER_WARP)

__device__ __forceinline__ float4 zero4() { return make_float4(0.f, 0.f, 0.f, 0.f); }

// Load one row of v (= u with Dirichlet ring zeroed) for this thread's 4 cols.
__device__ __forceinline__ float4 loadVrow(const float* __restrict__ u,
                                           size_t imgBase, int row, int col,
                                           bool zx, bool zw)
{
    if (row <= 0 || row >= GRID_H - 1) return zero4();   // ring rows + OOB guard
    float4 v = __ldcs(reinterpret_cast<const float4*>(u + imgBase + (size_t)row * GRID_W + col));
    if (zx) v.x = 0.f;
    if (zw) v.w = 0.f;
    return v;
}

__global__ __launch_bounds__(256)
void jacobi_roll_kernel(const float* __restrict__ u,
                        const float* __restrict__ f,
                        float* __restrict__ out)
{
    const int lane  = threadIdx.x & 31;
    const int gwarp = (blockIdx.x << 3) + (threadIdx.x >> 5);

    const int cb    = gwarp & (COLBLOCKS - 1);          // column block 0..7
    const int strip = (gwarp >> 3) & (STRIPS - 1);      // row strip
    const int b     = gwarp >> 10;                      // batch (8*128 warps per image)

    const int col = (cb << 7) + (lane << 2);            // first of 4 cols owned
    const int r0  = strip * ROWS_PER_WARP;

    const size_t imgBase = (size_t)b * GRID_H * GRID_W;

    // Ring-column zeroing predicates for this thread's float4.
    const bool zx = (cb == 0 && lane == 0);                 // owns col 0
    const bool zw = (cb == COLBLOCKS - 1 && lane == 31);    // owns col 1023
    // Warp-edge neighbor load predicates (left col cb*128-1, right col (cb+1)*128).
    const bool doLE = (lane == 0  && cb > 0);
    const bool doRE = (lane == 31 && cb < COLBLOCKS - 1);

    const float cof = -(1.0f / 1023.0f) * (1.0f / 1023.0f) * 0.25f;

    // Prologue: rows r0-1 and r0.
    float4 pv = loadVrow(u, imgBase, r0 - 1, col, zx, zw);
    float4 cv = loadVrow(u, imgBase, r0,     col, zx, zw);
    float lec = 0.f, rec = 0.f;
    if (r0 >= 1 && r0 <= GRID_H - 2) {
        if (doLE) lec = __ldcs(u + imgBase + (size_t)r0 * GRID_W + (cb << 7) - 1);
        if (doRE) rec = __ldcs(u + imgBase + (size_t)r0 * GRID_W + ((cb + 1) << 7));
    }

    #pragma unroll
    for (int i = 0; i < ROWS_PER_WARP; i++) {
        const int row = r0 + i;
        const size_t rowOff = imgBase + (size_t)row * GRID_W + col;

        // Fetch next row (+ its warp-edge scalars) early for MLP.
        float4 nv = loadVrow(u, imgBase, row + 1, col, zx, zw);
        float len = 0.f, ren = 0.f;
        if (row + 1 >= 1 && row + 1 <= GRID_H - 2) {
            if (doLE) len = __ldcs(u + imgBase + (size_t)(row + 1) * GRID_W + (cb << 7) - 1);
            if (doRE) ren = __ldcs(u + imgBase + (size_t)(row + 1) * GRID_W + ((cb + 1) << 7));
        }

        float4 o;
        if (row == 0 || row == GRID_H - 1) {
            o = zero4();
        } else {
            float4 fv = __ldcs(reinterpret_cast<const float4*>(f + rowOff));

            float lw = __shfl_up_sync(0xffffffffu, cv.w, 1);
            float rx = __shfl_down_sync(0xffffffffu, cv.x, 1);
            if (lane == 0)  lw = lec;   // left edge of warp strip (0 when cb==0: ring)
            if (lane == 31) rx = rec;   // right edge (0 when cb==7: ring)

            o.x = 0.25f * (pv.x + nv.x + lw   + cv.y) + cof * fv.x;
            o.y = 0.25f * (pv.y + nv.y + cv.x + cv.z) + cof * fv.y;
            o.z = 0.25f * (pv.z + nv.z + cv.y + cv.w) + cof * fv.z;
            o.w = 0.25f * (pv.w + nv.w + cv.z + rx  ) + cof * fv.w;

            if (zx) o.x = 0.f;          // Dirichlet columns stay 0
            if (zw) o.w = 0.f;
        }

        __stcs(reinterpret_cast<float4*>(out + rowOff), o);

        pv = cv; cv = nv; lec = len; rec = ren;
    }
}

extern "C" void kernel_launch(void* const* d_in, const int* in_sizes, int n_in,
                              void* d_out, int out_size)
{
    const float* u = (const float*)d_in[0];
    const float* f = (const float*)d_in[1];
    // d_in[2] is the fixed 3x3 cross stencil (0.25) — hardcoded.
    float* out = (float*)d_out;

    // total warps = BATCH * STRIPS * COLBLOCKS = 16*128*8 = 16384 -> 2048 blocks of 8 warps
    dim3 grid(BATCH * STRIPS * COLBLOCKS / 8);
    dim3 block(256);
    jacobi_roll_kernel<<<grid, block>>>(u, f, out);
}